// round 5
// baseline (speedup 1.0000x reference)
#include <cuda_runtime.h>

// B=2048, D=3706, total=B*D=7,589,888
// inputs: d_in[0] fake [B,D] f32; d_in[1] minb [D] f32; d_in[2] lens [D,4] f32
// output: dist f32 [B,D,6] then val f32 [B,D]
//
// b0=min[d]; b_{k+1}=b_k+relu(len[d,k])+1e-4 (strictly increasing)
// dist[r] = (r==0 || a>b[r-1]) && (r==5 || a<b[r]); a==b_k -> all zeros
// val = sum r*dist[r]
//
// R5 = R4 minus the smem staging (proven irrelevant to the DRAM write path:
// consecutive threads tile full 128B lines either way). Direct evict-first
// float2 stores; fake stays default-policy so it remains L2-resident across
// graph replays (the R4 win mechanism).

#define EPSK 1e-4f
#define TPB 256

__global__ void __launch_bounds__(TPB)
discret_kernel(const float* __restrict__ fake,
               const float* __restrict__ minb,
               const float4* __restrict__ lens,
               float* __restrict__ out_dist,   // [B*D*6]
               float* __restrict__ out_val,    // [B*D]
               int total, int D)
{
    int idx = blockIdx.x * TPB + threadIdx.x;
    if (idx >= total) return;

    int d = idx % D;

    float a  = fake[idx];                  // default policy -> L2-resident across replays
    float4 L = __ldg(&lens[d]);
    float b0 = __ldg(&minb[d]);
    float b1 = b0 + fmaxf(L.x, 0.0f) + EPSK;
    float b2 = b1 + fmaxf(L.y, 0.0f) + EPSK;
    float b3 = b2 + fmaxf(L.z, 0.0f) + EPSK;
    float b4 = b3 + fmaxf(L.w, 0.0f) + EPSK;

    float d0 = (a < b0)           ? 1.0f : 0.0f;
    float d1 = (a > b0 && a < b1) ? 1.0f : 0.0f;
    float d2 = (a > b1 && a < b2) ? 1.0f : 0.0f;
    float d3 = (a > b2 && a < b3) ? 1.0f : 0.0f;
    float d4 = (a > b3 && a < b4) ? 1.0f : 0.0f;
    float d5 = (a > b4)           ? 1.0f : 0.0f;

    float v = d1 + 2.0f * d2 + 3.0f * d3 + 4.0f * d4 + 5.0f * d5;

    // 24B slice at byte offset idx*24 (8-aligned): three STG.64, evict-first.
    // A warp's 3 stores still cover 768B of contiguous, fully-written lines.
    float2* p = reinterpret_cast<float2*>(out_dist + (size_t)idx * 6);
    __stcs(&p[0], make_float2(d0, d1));
    __stcs(&p[1], make_float2(d2, d3));
    __stcs(&p[2], make_float2(d4, d5));

    __stcs(&out_val[idx], v);
}

extern "C" void kernel_launch(void* const* d_in, const int* in_sizes, int n_in,
                              void* d_out, int out_size)
{
    const float*  fake = (const float*)d_in[0];
    const float*  minb = (const float*)d_in[1];
    const float4* lens = (const float4*)d_in[2];

    int total = in_sizes[0];          // B*D
    int D     = in_sizes[1];          // 3706

    float* out  = (float*)d_out;
    float* dist = out;                          // [B*D*6]
    float* val  = out + (size_t)total * 6;      // [B*D]

    int blocks = (total + TPB - 1) / TPB;
    discret_kernel<<<blocks, TPB>>>(fake, minb, lens, dist, val, total, D);
}

// round 6
// speedup vs baseline: 1.0451x; 1.0451x over previous
#include <cuda_runtime.h>
#include <cstdint>

// B=2048, D=3706, total=B*D=7,589,888 (divisible by 256)
// inputs: d_in[0] fake [B,D] f32; d_in[1] minb [D] f32; d_in[2] lens [D,4] f32
// output: dist f32 [B,D,6] then val f32 [B,D]
//
// b0=min[d]; b_{k+1}=b_k+relu(len[d,k])+1e-4 (strictly increasing)
// dist[r] = (r==0 || a>b[r-1]) && (r==5 || a<b[r]); a==b_k -> all zeros
// val = sum r*dist[r]
//
// R6 = R4 (smem-staged dist, evict-first policy) but the 6144B block tile is
// flushed with ONE cp.async.bulk TMA store (evict_first cache policy) instead
// of 384 LDS+STG pairs. fake stays default-policy -> L2-resident across graph
// replays (the R4 win). val stays per-thread __stcs (coalesced).

#define EPSK 1e-4f
#define TPB 256

__global__ void __launch_bounds__(TPB)
discret_kernel(const float* __restrict__ fake,
               const float* __restrict__ minb,
               const float4* __restrict__ lens,
               float* __restrict__ out_dist,   // [B*D*6]
               float* __restrict__ out_val,    // [B*D]
               int total, int D)
{
    __shared__ __align__(16) float sdist[TPB * 6];   // 6 KB, 16B-aligned

    int t   = threadIdx.x;
    int idx = blockIdx.x * TPB + t;

    float d0 = 0.f, d1 = 0.f, d2 = 0.f, d3 = 0.f, d4 = 0.f, d5 = 0.f;

    if (idx < total) {
        int d = idx % D;

        float a  = fake[idx];              // default policy: L2-resident across replays
        float4 L = __ldg(&lens[d]);
        float b0 = __ldg(&minb[d]);
        float b1 = b0 + fmaxf(L.x, 0.0f) + EPSK;
        float b2 = b1 + fmaxf(L.y, 0.0f) + EPSK;
        float b3 = b2 + fmaxf(L.z, 0.0f) + EPSK;
        float b4 = b3 + fmaxf(L.w, 0.0f) + EPSK;

        d0 = (a < b0)           ? 1.0f : 0.0f;
        d1 = (a > b0 && a < b1) ? 1.0f : 0.0f;
        d2 = (a > b1 && a < b2) ? 1.0f : 0.0f;
        d3 = (a > b2 && a < b3) ? 1.0f : 0.0f;
        d4 = (a > b3 && a < b4) ? 1.0f : 0.0f;
        d5 = (a > b4)           ? 1.0f : 0.0f;

        float v = d1 + 2.0f * d2 + 3.0f * d3 + 4.0f * d4 + 5.0f * d5;
        __stcs(&out_val[idx], v);          // evict-first
    }

    // stage into smem (stride-6 word writes: benign 2-way bank conflict)
    float* s = sdist + t * 6;
    s[0] = d0; s[1] = d1; s[2] = d2; s[3] = d3; s[4] = d4; s[5] = d5;
    __syncthreads();

    int block_first = blockIdx.x * TPB;
    int n_valid = total - block_first;

    if (n_valid >= TPB) {
        // One TMA bulk store: smem tile -> gmem, 6144 bytes, evict_first in L2.
        if (t == 0) {
            // order generic smem stores before async-proxy read
            asm volatile("fence.proxy.async.shared::cta;" ::: "memory");

            uint32_t saddr;
            asm("{ .reg .u64 x; cvta.to.shared.u64 x, %1; cvt.u32.u64 %0, x; }"
                : "=r"(saddr) : "l"(sdist));
            uint64_t gaddr = (uint64_t)(out_dist + (size_t)block_first * 6);

            asm volatile(
                "{\n\t"
                ".reg .b64 pol;\n\t"
                "createpolicy.fractional.L2::evict_first.b64 pol, 1.0;\n\t"
                "cp.async.bulk.global.shared::cta.bulk_group.L2::cache_hint "
                "[%0], [%1], %2, pol;\n\t"
                "cp.async.bulk.commit_group;\n\t"
                "cp.async.bulk.wait_group.read 0;\n\t"
                "}"
                :: "l"(gaddr), "r"(saddr), "n"(TPB * 6 * 4)
                : "memory");
        }
    } else {
        // tail block (unused for this shape, kept for generality)
        float* g = out_dist + (size_t)block_first * 6;
        for (int i = t; i < n_valid * 6; i += TPB)
            __stcs(&g[i], sdist[i]);
    }
}

extern "C" void kernel_launch(void* const* d_in, const int* in_sizes, int n_in,
                              void* d_out, int out_size)
{
    const float*  fake = (const float*)d_in[0];
    const float*  minb = (const float*)d_in[1];
    const float4* lens = (const float4*)d_in[2];

    int total = in_sizes[0];          // B*D
    int D     = in_sizes[1];          // 3706

    float* out  = (float*)d_out;
    float* dist = out;                          // [B*D*6]
    float* val  = out + (size_t)total * 6;      // [B*D]

    int blocks = (total + TPB - 1) / TPB;
    discret_kernel<<<blocks, TPB>>>(fake, minb, lens, dist, val, total, D);
}